// round 15
// baseline (speedup 1.0000x reference)
#include <cuda_runtime.h>
#include <cuda_bf16.h>
#include <cstdint>
#include <math.h>

typedef unsigned int       u32;
typedef unsigned long long u64;

#define S_MAX 20000
#define S_PAD 20096
#define D_FIX 256
#define CHUNK 32

// Scratch (device globals: allocation-free per harness rules; zero-init at load)
__device__ float g_pooled[S_MAX * D_FIX];       // raw Σ e_i x_i  [S,256]
__device__ float g_denom[S_MAX];                // raw Σ e_i      [S]
__device__ __nv_bfloat16 g_A2[S_PAD * 512];     // pooled bf16: [s][0:256)=hi, [256:512)=lo
__device__ __nv_bfloat16 g_Bhi[256 * 256];      // Wm^T hi  [n][k]
__device__ __nv_bfloat16 g_Blo[256 * 256];      // Wm^T lo  [n][k]

extern __shared__ char dyn_smem[];              // used by the GEMM only

__device__ __forceinline__ u32 smem_u32(const void* p) {
    u32 a;
    asm("{ .reg .u64 t; cvta.to.shared.u64 t, %1; cvt.u32.u64 %0, t; }" : "=r"(a) : "l"(p));
    return a;
}
__device__ __forceinline__ u32 pack_bf2(__nv_bfloat16 a, __nv_bfloat16 b) {
    return (u32)__bfloat16_as_ushort(a) | ((u32)__bfloat16_as_ushort(b) << 16);
}
__device__ __forceinline__ void cpasync16(u32 dst, const void* src) {
    asm volatile("cp.async.cg.shared.global [%0], [%1], 16;"
                 :: "r"(dst), "l"(src) : "memory");
}
__device__ __forceinline__ void ldsm4(u32* r, u32 addr) {
    asm volatile("ldmatrix.sync.aligned.m8n8.x4.shared.b16 {%0,%1,%2,%3}, [%4];"
                 : "=r"(r[0]), "=r"(r[1]), "=r"(r[2]), "=r"(r[3]) : "r"(addr));
}
__device__ __forceinline__ void mma_bf16(float* c, const u32* a, const u32* b) {
    asm volatile(
        "mma.sync.aligned.m16n8k16.row.col.f32.bf16.bf16.f32 "
        "{%0,%1,%2,%3}, {%4,%5,%6,%7}, {%8,%9}, {%0,%1,%2,%3};"
        : "+f"(c[0]), "+f"(c[1]), "+f"(c[2]), "+f"(c[3])
        : "r"(a[0]), "r"(a[1]), "r"(a[2]), "r"(a[3]), "r"(b[0]), "r"(b[1]));
}

// ===========================================================================
// Kernel P: split Wm^T into bf16 hi/lo AND zero g_denom/g_pooled (runs
// immediately before the pool so the zeroed lines are L2-hot for its atomics)
// ===========================================================================
__global__ void __launch_bounds__(256) prep_b_kernel(const float* __restrict__ Wm) {
    const int n = blockIdx.x;      // 0..255
    const int k = threadIdx.x;     // 0..255
    const float v = Wm[k * 256 + n];
    const __nv_bfloat16 hi = __float2bfloat16(v);
    const __nv_bfloat16 lo = __float2bfloat16(v - __bfloat162float(hi));
    g_Bhi[n * 256 + k] = hi;
    g_Blo[n * 256 + k] = lo;

    const int tid = n * 256 + k;   // 0..65535
    if (tid < S_MAX) g_denom[tid] = 0.f;
    const float4 z = make_float4(0.f, 0.f, 0.f, 0.f);
    float4* gp = (float4*)g_pooled;
    #pragma unroll 4
    for (int i = tid; i < S_MAX * 64; i += 65536) gp[i] = z;
}

// ===========================================================================
// Kernel A: register-resident node pooling. Thread t owns dim t; xv[j] for
// the CTA's 32 nodes live in registers (coalesced LDGs, deep MLP). Gate dots
// via warp shuffle-reduce + 1KB smem combine; pass 2 accumulates from regs.
// Tiny smem -> 8 CTAs/SM (thread-capped); no 32KB staging round-trip.
// ===========================================================================
__global__ void __launch_bounds__(256) node_pool_kernel(
    const float* __restrict__ x,
    const float* __restrict__ weights,
    const float* __restrict__ Wg,
    const float* __restrict__ bg,
    const float* __restrict__ p_,
    const int*   __restrict__ index,
    int N)
{
    __shared__ float part[CHUNK * 8];    // [j][w]
    __shared__ float es[CHUNK];
    __shared__ int   idxs[CHUNK + 1];

    const int base = blockIdx.x * CHUNK;
    const int len  = min(CHUNK, N - base);
    const int t = threadIdx.x;
    const int w = t >> 5;
    const int l = t & 31;

    if (t < len) idxs[t] = index[base + t];
    if (t == 0)  idxs[len] = -1;

    // load the CTA's 32 rows, dim t, into registers (coalesced; front-batched)
    float xv[CHUNK];
    const float* xp = x + (size_t)base * 256 + t;
    #pragma unroll
    for (int j = 0; j < CHUNK; j++)
        xv[j] = (j < len) ? __ldcs(xp + j * 256) : 0.f;

    // gate partial dots: warp reduce over lanes, 8 warp-partials to smem
    const float Wgt = Wg[t];
    #pragma unroll
    for (int j = 0; j < CHUNK; j++) {
        float p = xv[j] * Wgt;
        #pragma unroll
        for (int off = 16; off; off >>= 1)
            p += __shfl_xor_sync(0xffffffffu, p, off);
        if (l == 0) part[j * 8 + w] = p;
    }
    __syncthreads();

    // warp 0: finish dots, compute e, flush denominators
    if (t < CHUNK) {
        float sum = 0.f;
        #pragma unroll
        for (int ww = 0; ww < 8; ww++) sum += part[t * 8 + ww];
        float e = 0.f;
        if (t < len) {
            const float wv = __ldg(&weights[base + t]);
            e = expf(fmaf(p_[0], logf(wv), sum + bg[0]));
            atomicAdd(&g_denom[idxs[t]], e);
        }
        es[t] = e;
    }
    __syncthreads();

    // pass 2: accumulate e*x from REGISTERS, atomic flush at boundaries
    float acc = 0.f;
    int cur = idxs[0];
    for (int j = 0; j < len; j++) {
        acc = fmaf(es[j], xv[j], acc);
        const int nxt = idxs[j + 1];
        if (nxt != cur) {
            atomicAdd(&g_pooled[(size_t)cur * 256 + t], acc);
            acc = 0.f;
            cur = nxt;
        }
    }
}

// ===========================================================================
// Kernel C: convert pooled fp32 -> bf16 hi|lo; zero-fill padded rows
// ===========================================================================
__global__ void __launch_bounds__(256) convert_a_kernel(int S) {
    const int idx = blockIdx.x * 256 + threadIdx.x;
    if (idx >= S_PAD * 64) return;
    const int row = idx >> 6;
    const int c4  = idx & 63;
    float4 v = make_float4(0.f, 0.f, 0.f, 0.f);
    if (row < S) v = ((const float4*)g_pooled)[idx];
    const __nv_bfloat16 h0 = __float2bfloat16(v.x);
    const __nv_bfloat16 h1 = __float2bfloat16(v.y);
    const __nv_bfloat16 h2 = __float2bfloat16(v.z);
    const __nv_bfloat16 h3 = __float2bfloat16(v.w);
    const __nv_bfloat16 l0 = __float2bfloat16(v.x - __bfloat162float(h0));
    const __nv_bfloat16 l1 = __float2bfloat16(v.y - __bfloat162float(h1));
    const __nv_bfloat16 l2 = __float2bfloat16(v.z - __bfloat162float(h2));
    const __nv_bfloat16 l3 = __float2bfloat16(v.w - __bfloat162float(h3));
    *(uint2*)&g_A2[(size_t)row * 512 + c4 * 4] =
        make_uint2(pack_bf2(h0, h1), pack_bf2(h2, h3));
    *(uint2*)&g_A2[(size_t)row * 512 + 256 + c4 * 4] =
        make_uint2(pack_bf2(l0, l1), pack_bf2(l2, l3));
}

// ===========================================================================
// Kernel B: bf16 mma.sync GEMM, virtual K = 768 (hi*hi + lo*hi + hi*lo).
// BM=64, BN=128, BK=64; 4 CTAs/SM; cp.async double buffer; ldmatrix.
// (measured 40us in R14 — kept unchanged this round)
// ===========================================================================
#define GBM 64
#define GBN 128
#define ASTR 72
#define ATB (GBM * ASTR * 2)
#define BTB (GBN * ASTR * 2)
#define GEMM_SMEM (2 * ATB + 2 * BTB)

__global__ void __launch_bounds__(256, 4) mma_gemm_kernel(
    const float* __restrict__ bmv_,
    float* __restrict__ out,
    int S)
{
    const u32 sbase = smem_u32(dyn_smem);
    const int t = threadIdx.x;
    const int lane = t & 31;
    const int w = t >> 5;
    const int warpM = w & 3;
    const int warpN = w >> 2;
    const int lr = lane >> 2;
    const int lc = lane & 3;
    const int q  = lane >> 3;
    const int mr = lane & 7;

    const int aro = (q & 1) * 8 + mr;
    const int ako = (q >> 1) * 8;
    const int bro = (q >> 1) * 8 + mr;
    const int bko = (q & 1) * 8;

    const int rowBase = blockIdx.x * GBM;
    const int colBase = blockIdx.y * GBN;

    const int sr  = t >> 3;
    const int sk8 = (t & 7) * 8;

    float c[8][4];
    #pragma unroll
    for (int j = 0; j < 8; j++)
        #pragma unroll
        for (int qq = 0; qq < 4; qq++) c[j][qq] = 0.f;

    auto stage = [&](int ch, int buf) {
        const int kc = ch & 3;
        const int acol = kc * 64 + ((ch >= 4 && ch < 8) ? 256 : 0);
        const __nv_bfloat16* Bb = (ch < 8) ? g_Bhi : g_Blo;
        const u32 abase = sbase + buf * ATB;
        const u32 bbase = sbase + 2 * ATB + buf * BTB;
        #pragma unroll
        for (int i = 0; i < 2; i++) {
            const int r = sr + i * 32;
            cpasync16(abase + r * (ASTR * 2) + sk8 * 2,
                      &g_A2[(size_t)(rowBase + r) * 512 + acol + sk8]);
        }
        #pragma unroll
        for (int i = 0; i < 4; i++) {
            const int r = sr + i * 32;
            cpasync16(bbase + r * (ASTR * 2) + sk8 * 2,
                      &Bb[(size_t)(colBase + r) * 256 + kc * 64 + sk8]);
        }
        asm volatile("cp.async.commit_group;" ::: "memory");
    };

    stage(0, 0);

    for (int ch = 0; ch < 12; ch++) {
        const int buf = ch & 1;
        if (ch + 1 < 12) {
            stage(ch + 1, buf ^ 1);
            asm volatile("cp.async.wait_group 1;" ::: "memory");
        } else {
            asm volatile("cp.async.wait_group 0;" ::: "memory");
        }
        __syncthreads();

        const u32 abase = sbase + buf * ATB;
        const u32 bbase = sbase + 2 * ATB + buf * BTB;
        #pragma unroll
        for (int kk = 0; kk < 4; kk++) {
            const int k0 = kk * 16;
            u32 a[4], b[4][4];
            ldsm4(a, abase + (warpM * 16 + aro) * (ASTR * 2) + (k0 + ako) * 2);
            #pragma unroll
            for (int jp = 0; jp < 4; jp++)
                ldsm4(b[jp], bbase + (warpN * 64 + jp * 16 + bro) * (ASTR * 2)
                                   + (k0 + bko) * 2);
            #pragma unroll
            for (int jp = 0; jp < 4; jp++) {
                mma_bf16(c[2 * jp],     a, &b[jp][0]);
                mma_bf16(c[2 * jp + 1], a, &b[jp][2]);
            }
        }
        __syncthreads();
    }

    {
        const int r0 = rowBase + warpM * 16 + lr;
        const int r1 = r0 + 8;
        float inv0 = 0.f, sg0 = 0.f, inv1 = 0.f, sg1 = 0.f;
        if (r0 < S) {
            const float d = g_denom[r0];
            inv0 = __fdividef(1.f, d + 1e-10f); sg0 = d * inv0;
        }
        if (r1 < S) {
            const float d = g_denom[r1];
            inv1 = __fdividef(1.f, d + 1e-10f); sg1 = d * inv1;
        }
        #pragma unroll
        for (int j = 0; j < 8; j++) {
            const int n = colBase + warpN * 64 + j * 8 + lc * 2;
            const float2 bm2 = *(const float2*)&bmv_[n];
            if (r0 < S) {
                float2 o;
                o.x = fmaf(c[j][0], inv0, sg0 * bm2.x);
                o.y = fmaf(c[j][1], inv0, sg0 * bm2.y);
                *(float2*)&out[(size_t)r0 * 256 + n] = o;
            }
            if (r1 < S) {
                float2 o;
                o.x = fmaf(c[j][2], inv1, sg1 * bm2.x);
                o.y = fmaf(c[j][3], inv1, sg1 * bm2.y);
                *(float2*)&out[(size_t)r1 * 256 + n] = o;
            }
        }
    }
}

// ===========================================================================
// inputs (metadata order): x, weights, Wg, bg, Wm, bm, p, index, [num_segments]
// ===========================================================================
extern "C" void kernel_launch(void* const* d_in, const int* in_sizes, int n_in,
                              void* d_out, int out_size) {
    const float* x       = (const float*)d_in[0];
    const float* weights = (const float*)d_in[1];
    const float* Wg      = (const float*)d_in[2];
    const float* bg      = (const float*)d_in[3];
    const float* Wm      = (const float*)d_in[4];
    const float* bm      = (const float*)d_in[5];
    const float* p       = (const float*)d_in[6];
    const int*   index   = (const int*)d_in[7];

    const int N = in_sizes[7];
    const int D = in_sizes[2];            // 256
    int S = out_size / D;                 // 20000
    if (S > S_MAX) S = S_MAX;

    cudaFuncSetAttribute(mma_gemm_kernel,
                         cudaFuncAttributeMaxDynamicSharedMemorySize, GEMM_SMEM);

    prep_b_kernel<<<256, 256>>>(Wm);      // also zeroes g_denom + g_pooled
    node_pool_kernel<<<(N + CHUNK - 1) / CHUNK, 256>>>(
        x, weights, Wg, bg, p, index, N);
    convert_a_kernel<<<(S_PAD * 64 + 255) / 256, 256>>>(S);
    dim3 grid((S + GBM - 1) / GBM, D / GBN);
    mma_gemm_kernel<<<grid, 256, GEMM_SMEM>>>(bm, (float*)d_out, S);
}

// round 16
// speedup vs baseline: 1.2814x; 1.2814x over previous
#include <cuda_runtime.h>
#include <cuda_bf16.h>
#include <cstdint>
#include <math.h>

typedef unsigned int       u32;
typedef unsigned long long u64;

#define S_MAX 20000
#define S_PAD 20096
#define D_FIX 256
#define CHUNK 32             // pool: best-measured config (R10)
#define POOL_SMEM (CHUNK * 256 * 4 + CHUNK * 4 + (CHUNK + 1) * 4)

// Scratch (device globals: allocation-free per harness rules; zero-init at load)
__device__ float g_pooled[S_MAX * D_FIX];       // raw Σ e_i x_i  [S,256]
__device__ float g_denom[S_MAX];                // raw Σ e_i      [S]
__device__ __nv_bfloat16 g_A2[S_PAD * 512];     // pooled bf16: [s][0:256)=hi, [256:512)=lo
__device__ __nv_bfloat16 g_Bhi[256 * 256];      // Wm^T hi  [n][k]
__device__ __nv_bfloat16 g_Blo[256 * 256];      // Wm^T lo  [n][k]

extern __shared__ char dyn_smem[];

__device__ __forceinline__ u32 smem_u32(const void* p) {
    u32 a;
    asm("{ .reg .u64 t; cvta.to.shared.u64 t, %1; cvt.u32.u64 %0, t; }" : "=r"(a) : "l"(p));
    return a;
}
__device__ __forceinline__ u32 pack_bf2(__nv_bfloat16 a, __nv_bfloat16 b) {
    return (u32)__bfloat16_as_ushort(a) | ((u32)__bfloat16_as_ushort(b) << 16);
}
__device__ __forceinline__ void cpasync16(u32 dst, const void* src) {
    asm volatile("cp.async.cg.shared.global [%0], [%1], 16;"
                 :: "r"(dst), "l"(src) : "memory");
}
__device__ __forceinline__ void ldsm4(u32* r, u32 addr) {
    asm volatile("ldmatrix.sync.aligned.m8n8.x4.shared.b16 {%0,%1,%2,%3}, [%4];"
                 : "=r"(r[0]), "=r"(r[1]), "=r"(r[2]), "=r"(r[3]) : "r"(addr));
}
__device__ __forceinline__ void mma_bf16(float* c, const u32* a, const u32* b) {
    asm volatile(
        "mma.sync.aligned.m16n8k16.row.col.f32.bf16.bf16.f32 "
        "{%0,%1,%2,%3}, {%4,%5,%6,%7}, {%8,%9}, {%0,%1,%2,%3};"
        : "+f"(c[0]), "+f"(c[1]), "+f"(c[2]), "+f"(c[3])
        : "r"(a[0]), "r"(a[1]), "r"(a[2]), "r"(a[3]), "r"(b[0]), "r"(b[1]));
}

// ===========================================================================
// Kernel P: split Wm^T into bf16 hi/lo AND zero g_denom + g_pooled.
// Runs immediately before the pool so zeroed lines are L2-hot for atomics.
// ===========================================================================
__global__ void __launch_bounds__(256) prep_b_kernel(const float* __restrict__ Wm) {
    const int n = blockIdx.x;      // 0..255
    const int k = threadIdx.x;     // 0..255
    const float v = Wm[k * 256 + n];
    const __nv_bfloat16 hi = __float2bfloat16(v);
    const __nv_bfloat16 lo = __float2bfloat16(v - __bfloat162float(hi));
    g_Bhi[n * 256 + k] = hi;
    g_Blo[n * 256 + k] = lo;

    const int tid = n * 256 + k;   // 0..65535
    if (tid < S_MAX) g_denom[tid] = 0.f;
    const float4 z = make_float4(0.f, 0.f, 0.f, 0.f);
    float4* gp = (float4*)g_pooled;
    #pragma unroll 4
    for (int i = tid; i < S_MAX * 64; i += 65536) gp[i] = z;
}

// ===========================================================================
// Kernel A: node-parallel fused gate + weighted pooling (EXACT R10 structure
// — the best-measured pool: smem staging, 6 CTAs/SM phase-staggered).
// ===========================================================================
__global__ void __launch_bounds__(256) node_pool_kernel(
    const float* __restrict__ x,
    const float* __restrict__ weights,
    const float* __restrict__ Wg,
    const float* __restrict__ bg,
    const float* __restrict__ p_,
    const int*   __restrict__ index,
    int N)
{
    float* xs  = (float*)dyn_smem;
    float* es  = xs + CHUNK * 256;
    int*   idxs = (int*)(es + CHUNK);

    const int base = blockIdx.x * CHUNK;
    const int len  = min(CHUNK, N - base);
    const int t = threadIdx.x;
    const int w = t >> 5;
    const int l = t & 31;

    if (t < len) idxs[t] = index[base + t];
    if (t == 0)  idxs[len] = -1;

    {
        const float4* src = (const float4*)x + (size_t)base * 64;
        float4* dst = (float4*)xs;
        const int n4 = len * 64;
        #pragma unroll 8
        for (int i = t; i < n4; i += 256) dst[i] = __ldcs(src + i);
    }
    __syncthreads();

    const float4* Wg4 = (const float4*)Wg;
    const float4 wga = Wg4[l];
    const float4 wgb = Wg4[32 + l];
    const float bgv = bg[0];
    const float pv  = p_[0];

    const int NJJ = CHUNK / 8;
    float pdv[NJJ], wv[NJJ];
    const float4* xs4 = (const float4*)xs;
    #pragma unroll
    for (int jj = 0; jj < NJJ; jj++) {
        const int j = w + jj * 8;
        pdv[jj] = 0.f; wv[jj] = 1.f;
        if (j < len) {
            const float4 xa = xs4[j * 64 + l];
            const float4 xb = xs4[j * 64 + 32 + l];
            pdv[jj] = xa.x * wga.x + xa.y * wga.y + xa.z * wga.z + xa.w * wga.w
                    + xb.x * wgb.x + xb.y * wgb.y + xb.z * wgb.z + xb.w * wgb.w;
            wv[jj] = __ldg(&weights[base + j]);
        }
    }
    #pragma unroll
    for (int jj = 0; jj < NJJ; jj++) {
        float pd = pdv[jj];
        #pragma unroll
        for (int off = 16; off; off >>= 1)
            pd += __shfl_xor_sync(0xffffffffu, pd, off);
        pdv[jj] = pd;
    }
    #pragma unroll
    for (int jj = 0; jj < NJJ; jj++) {
        const int j = w + jj * 8;
        if (j < len && l == 0)
            es[j] = expf(fmaf(pv, logf(wv[jj]), pdv[jj] + bgv));
    }
    __syncthreads();

    // denominators: one atomic per node, warp-parallel (t < len <= 32)
    if (t < len) atomicAdd(&g_denom[idxs[t]], es[t]);

    // thread-per-dim weighted accumulation + boundary flush
    {
        float acc = 0.f;
        int cur = idxs[0];
        for (int j = 0; j < len; j++) {
            acc = fmaf(es[j], xs[j * 256 + t], acc);
            const int nxt = idxs[j + 1];
            if (nxt != cur) {
                atomicAdd(&g_pooled[(size_t)cur * 256 + t], acc);
                acc = 0.f;
                cur = nxt;
            }
        }
    }
}

// ===========================================================================
// Kernel C: convert pooled fp32 -> bf16 hi|lo; zero-fill padded rows
// ===========================================================================
__global__ void __launch_bounds__(256) convert_a_kernel(int S) {
    const int idx = blockIdx.x * 256 + threadIdx.x;
    if (idx >= S_PAD * 64) return;
    const int row = idx >> 6;
    const int c4  = idx & 63;
    float4 v = make_float4(0.f, 0.f, 0.f, 0.f);
    if (row < S) v = ((const float4*)g_pooled)[idx];
    const __nv_bfloat16 h0 = __float2bfloat16(v.x);
    const __nv_bfloat16 h1 = __float2bfloat16(v.y);
    const __nv_bfloat16 h2 = __float2bfloat16(v.z);
    const __nv_bfloat16 h3 = __float2bfloat16(v.w);
    const __nv_bfloat16 l0 = __float2bfloat16(v.x - __bfloat162float(h0));
    const __nv_bfloat16 l1 = __float2bfloat16(v.y - __bfloat162float(h1));
    const __nv_bfloat16 l2 = __float2bfloat16(v.z - __bfloat162float(h2));
    const __nv_bfloat16 l3 = __float2bfloat16(v.w - __bfloat162float(h3));
    *(uint2*)&g_A2[(size_t)row * 512 + c4 * 4] =
        make_uint2(pack_bf2(h0, h1), pack_bf2(h2, h3));
    *(uint2*)&g_A2[(size_t)row * 512 + 256 + c4 * 4] =
        make_uint2(pack_bf2(l0, l1), pack_bf2(l2, l3));
}

// ===========================================================================
// Kernel B: bf16 mma.sync GEMM, virtual K = 768 (hi*hi + lo*hi + hi*lo).
// BM=64, BN=128, BK=64; 4 CTAs/SM; cp.async double buffer; ldmatrix
// (measured 39.4us in R15). Epilogue fuses 1/denom and bm.
// ===========================================================================
#define GBM 64
#define GBN 128
#define ASTR 72
#define ATB (GBM * ASTR * 2)
#define BTB (GBN * ASTR * 2)
#define GEMM_SMEM (2 * ATB + 2 * BTB)

__global__ void __launch_bounds__(256, 4) mma_gemm_kernel(
    const float* __restrict__ bmv_,
    float* __restrict__ out,
    int S)
{
    const u32 sbase = smem_u32(dyn_smem);
    const int t = threadIdx.x;
    const int lane = t & 31;
    const int w = t >> 5;
    const int warpM = w & 3;
    const int warpN = w >> 2;
    const int lr = lane >> 2;
    const int lc = lane & 3;
    const int q  = lane >> 3;
    const int mr = lane & 7;

    const int aro = (q & 1) * 8 + mr;
    const int ako = (q >> 1) * 8;
    const int bro = (q >> 1) * 8 + mr;
    const int bko = (q & 1) * 8;

    const int rowBase = blockIdx.x * GBM;
    const int colBase = blockIdx.y * GBN;

    const int sr  = t >> 3;
    const int sk8 = (t & 7) * 8;

    float c[8][4];
    #pragma unroll
    for (int j = 0; j < 8; j++)
        #pragma unroll
        for (int qq = 0; qq < 4; qq++) c[j][qq] = 0.f;

    auto stage = [&](int ch, int buf) {
        const int kc = ch & 3;
        const int acol = kc * 64 + ((ch >= 4 && ch < 8) ? 256 : 0);
        const __nv_bfloat16* Bb = (ch < 8) ? g_Bhi : g_Blo;
        const u32 abase = sbase + buf * ATB;
        const u32 bbase = sbase + 2 * ATB + buf * BTB;
        #pragma unroll
        for (int i = 0; i < 2; i++) {
            const int r = sr + i * 32;
            cpasync16(abase + r * (ASTR * 2) + sk8 * 2,
                      &g_A2[(size_t)(rowBase + r) * 512 + acol + sk8]);
        }
        #pragma unroll
        for (int i = 0; i < 4; i++) {
            const int r = sr + i * 32;
            cpasync16(bbase + r * (ASTR * 2) + sk8 * 2,
                      &Bb[(size_t)(colBase + r) * 256 + kc * 64 + sk8]);
        }
        asm volatile("cp.async.commit_group;" ::: "memory");
    };

    stage(0, 0);

    for (int ch = 0; ch < 12; ch++) {
        const int buf = ch & 1;
        if (ch + 1 < 12) {
            stage(ch + 1, buf ^ 1);
            asm volatile("cp.async.wait_group 1;" ::: "memory");
        } else {
            asm volatile("cp.async.wait_group 0;" ::: "memory");
        }
        __syncthreads();

        const u32 abase = sbase + buf * ATB;
        const u32 bbase = sbase + 2 * ATB + buf * BTB;
        #pragma unroll
        for (int kk = 0; kk < 4; kk++) {
            const int k0 = kk * 16;
            u32 a[4], b[4][4];
            ldsm4(a, abase + (warpM * 16 + aro) * (ASTR * 2) + (k0 + ako) * 2);
            #pragma unroll
            for (int jp = 0; jp < 4; jp++)
                ldsm4(b[jp], bbase + (warpN * 64 + jp * 16 + bro) * (ASTR * 2)
                                   + (k0 + bko) * 2);
            #pragma unroll
            for (int jp = 0; jp < 4; jp++) {
                mma_bf16(c[2 * jp],     a, &b[jp][0]);
                mma_bf16(c[2 * jp + 1], a, &b[jp][2]);
            }
        }
        __syncthreads();
    }

    {
        const int r0 = rowBase + warpM * 16 + lr;
        const int r1 = r0 + 8;
        float inv0 = 0.f, sg0 = 0.f, inv1 = 0.f, sg1 = 0.f;
        if (r0 < S) {
            const float d = g_denom[r0];
            inv0 = __fdividef(1.f, d + 1e-10f); sg0 = d * inv0;
        }
        if (r1 < S) {
            const float d = g_denom[r1];
            inv1 = __fdividef(1.f, d + 1e-10f); sg1 = d * inv1;
        }
        #pragma unroll
        for (int j = 0; j < 8; j++) {
            const int n = colBase + warpN * 64 + j * 8 + lc * 2;
            const float2 bm2 = *(const float2*)&bmv_[n];
            if (r0 < S) {
                float2 o;
                o.x = fmaf(c[j][0], inv0, sg0 * bm2.x);
                o.y = fmaf(c[j][1], inv0, sg0 * bm2.y);
                *(float2*)&out[(size_t)r0 * 256 + n] = o;
            }
            if (r1 < S) {
                float2 o;
                o.x = fmaf(c[j][2], inv1, sg1 * bm2.x);
                o.y = fmaf(c[j][3], inv1, sg1 * bm2.y);
                *(float2*)&out[(size_t)r1 * 256 + n] = o;
            }
        }
    }
}

// ===========================================================================
// inputs (metadata order): x, weights, Wg, bg, Wm, bm, p, index, [num_segments]
// ===========================================================================
extern "C" void kernel_launch(void* const* d_in, const int* in_sizes, int n_in,
                              void* d_out, int out_size) {
    const float* x       = (const float*)d_in[0];
    const float* weights = (const float*)d_in[1];
    const float* Wg      = (const float*)d_in[2];
    const float* bg      = (const float*)d_in[3];
    const float* Wm      = (const float*)d_in[4];
    const float* bm      = (const float*)d_in[5];
    const float* p       = (const float*)d_in[6];
    const int*   index   = (const int*)d_in[7];

    const int N = in_sizes[7];
    const int D = in_sizes[2];            // 256
    int S = out_size / D;                 // 20000
    if (S > S_MAX) S = S_MAX;

    cudaFuncSetAttribute(mma_gemm_kernel,
                         cudaFuncAttributeMaxDynamicSharedMemorySize, GEMM_SMEM);

    prep_b_kernel<<<256, 256>>>(Wm);      // also zeroes g_denom + g_pooled (L2-hot)
    node_pool_kernel<<<(N + CHUNK - 1) / CHUNK, 256, POOL_SMEM>>>(
        x, weights, Wg, bg, p, index, N);
    convert_a_kernel<<<(S_PAD * 64 + 255) / 256, 256>>>(S);
    dim3 grid((S + GBM - 1) / GBM, D / GBN);
    mma_gemm_kernel<<<grid, 256, GEMM_SMEM>>>(bm, (float*)d_out, S);
}